// round 14
// baseline (speedup 1.0000x reference)
#include <cuda_runtime.h>
#include <cuda_bf16.h>

// YOLO layer: x [B=16, C=255, 64, 64] fp32, anchors [3,2] fp32.
// pred = x.reshape(B, 3, 85, 64, 64).transpose(0,1,3,4,2)
// Outputs concatenated in d_out (float32):
//   boxes [B,3,64,64,4]  : 786,432    elems at offset 0
//   conf  [B,3,64,64]    : 196,608    elems at offset 786,432
//   cls   [B,3,64,64,80] : 15,728,640 elems at offset 983,040
//
// R13: complete the L2 residency inversion. R12 (evict_last stores
// only) was flat because default-priority input loads still fought the
// output for L2 (133.6MB streams > 126MB L2) -> output writebacks
// (66.8MB/replay) remained the DRAM bottleneck. This round ALSO marks
// input loads ld.global.nc.L2::evict_first.v8.b32: input recycles a
// small L2 slice, output (66.8MB < 126MB) stays resident, dirty lines
// are re-dirtied in place across graph replays -> DRAM becomes a
// ~67MB/replay read-dominated stream (no turnaround penalty).
// sm_103a requires 256-bit width for L2 eviction hints on both ld/st.
// sigmoid via MUFU.TANH: sig(x) = fma(0.5, tanh(0.5x), 0.5).

#define NT 256
#define TP 64
#define PITCH 68            // floats per smem row: float4-aligned, bank stride 4
#define PITCH4 17

__device__ __forceinline__ float sigf(float v) {
    float t;
    asm("tanh.approx.f32 %0, %1;" : "=f"(t) : "f"(v * 0.5f));
    return fmaf(0.5f, t, 0.5f);
}

__device__ __forceinline__ void st_el_f8(float* p, const float* v) {
    asm volatile(
        "st.global.L2::evict_last.v8.b32 [%0], {%1,%2,%3,%4,%5,%6,%7,%8};"
        :: "l"(p),
           "r"(__float_as_uint(v[0])), "r"(__float_as_uint(v[1])),
           "r"(__float_as_uint(v[2])), "r"(__float_as_uint(v[3])),
           "r"(__float_as_uint(v[4])), "r"(__float_as_uint(v[5])),
           "r"(__float_as_uint(v[6])), "r"(__float_as_uint(v[7]))
        : "memory");
}

__device__ __forceinline__ void ld_ef_f8(const float* p, float* v) {
    unsigned a0, a1, a2, a3, a4, a5, a6, a7;
    asm("ld.global.nc.L2::evict_first.v8.b32 {%0,%1,%2,%3,%4,%5,%6,%7}, [%8];"
        : "=r"(a0), "=r"(a1), "=r"(a2), "=r"(a3),
          "=r"(a4), "=r"(a5), "=r"(a6), "=r"(a7)
        : "l"(p));
    v[0] = __uint_as_float(a0); v[1] = __uint_as_float(a1);
    v[2] = __uint_as_float(a2); v[3] = __uint_as_float(a3);
    v[4] = __uint_as_float(a4); v[5] = __uint_as_float(a5);
    v[6] = __uint_as_float(a6); v[7] = __uint_as_float(a7);
}

__global__ __launch_bounds__(NT) void yolo_kernel(
    const float* __restrict__ x,
    const float* __restrict__ anchors,
    float* __restrict__ out)
{
    constexpr int A    = 3;
    constexpr int CH   = 85;
    constexpr int P    = 64 * 64;                     // 4096 positions per (b,a)
    constexpr int Btot = 16;
    constexpr int CONF_OFF = Btot * A * P * 4;        // 786432
    constexpr int CLS_OFF  = CONF_OFF + Btot * A * P; // 983040

    __shared__ float tile[CH * PITCH];                // 85 x 68 floats = 23.1 KB

    const int blk = blockIdx.x;
    const int ba  = blk >> 6;                         // 64 tiles per (b,a)
    const int p0  = (blk & 63) * TP;
    const int t   = threadIdx.x;

    // ---- Load: 85 ch x 8 chunks of 32B, evict_first v8 loads ----
    // Per-tile input = 85 rows x 256B, row base 256B-aligned.
    const float* xin = x + (size_t)ba * CH * P + p0;
    #pragma unroll
    for (int k = 0; k < 3; k++) {
        const int f = t + k * NT;                     // chunk id, need < 680
        if (k < 2 || f < 680) {
            const int c  = f >> 3;                    // channel (0..84)
            const int q8 = f & 7;                     // 32B chunk in row
            float v[8];
            ld_ef_f8(xin + (size_t)c * P + 8 * q8, v);
            float* dst = tile + c * PITCH + 8 * q8;
            #pragma unroll
            for (int i = 0; i < 8; i++) dst[i] = v[i];
        }
    }
    __syncthreads();

    // ---- cls: 640 x 32B chunks, output-linear; warp store = 1KB contig ----
    {
        float* ocls = out + CLS_OFF + (size_t)(ba * P + p0) * 80;
        #pragma unroll
        for (int k = 0; k < 3; k++) {
            const int f = t + k * NT;                 // chunk id, need < 640
            if (k < 2 || f < 640) {
                const int p  = f / 10;                // position in tile (0..63)
                const int j8 = f - 10 * p;            // 32B chunk in position (0..9)
                const int c  = 5 + 8 * j8;            // channels c..c+7
                float o[8];
                #pragma unroll
                for (int i = 0; i < 8; i++)
                    o[i] = sigf(tile[(c + i) * PITCH + p]);
                st_el_f8(ocls + (size_t)f * 8, o);
            }
        }
    }

    // ---- boxes: lanes 0..31, 2 positions (32B) each; warp = 1KB contig ----
    if (t < 32) {
        const int a  = ba - (ba / A) * A;
        const float aw = __ldg(anchors + a * 2 + 0);
        const float ah = __ldg(anchors + a * 2 + 1);
        float o[8];
        #pragma unroll
        for (int h = 0; h < 2; h++) {
            const int p  = 2 * t + h;
            const int pg = p0 + p;
            o[4*h + 0] = (sigf(tile[0 * PITCH + p]) + (float)(pg >> 6)) * (1.0f / 64.0f);
            o[4*h + 1] = (sigf(tile[1 * PITCH + p]) + (float)(pg & 63)) * (1.0f / 64.0f);
            o[4*h + 2] = __expf(tile[2 * PITCH + p]) * aw;
            o[4*h + 3] = __expf(tile[3 * PITCH + p]) * ah;
        }
        st_el_f8(out + (size_t)(ba * P + p0 + 2 * t) * 4, o);
    }
    // ---- conf: threads 32..39, 8 floats each; 256B contiguous ----
    else if (t < 40) {
        const int q = t - 32;                         // 0..7
        float o[8];
        #pragma unroll
        for (int i = 0; i < 8; i++)
            o[i] = sigf(tile[4 * PITCH + 8 * q + i]);
        st_el_f8(out + CONF_OFF + ba * P + p0 + 8 * q, o);
    }
}

extern "C" void kernel_launch(void* const* d_in, const int* in_sizes, int n_in,
                              void* d_out, int out_size) {
    const float* x       = (const float*)d_in[0];
    const float* anchors = (const float*)d_in[1];
    float*       out     = (float*)d_out;
    yolo_kernel<<<3072, NT>>>(x, anchors, out);
}

// round 15
// speedup vs baseline: 1.5296x; 1.5296x over previous
#include <cuda_runtime.h>
#include <cuda_bf16.h>

// YOLO layer: x [B=16, C=255, 64, 64] fp32, anchors [3,2] fp32.
// pred = x.reshape(B, 3, 85, 64, 64).transpose(0,1,3,4,2)
// Outputs concatenated in d_out (float32):
//   boxes [B,3,64,64,4]  : 786,432    elems at offset 0
//   conf  [B,3,64,64]    : 196,608    elems at offset 786,432
//   cls   [B,3,64,64,80] : 15,728,640 elems at offset 983,040
//
// R14: L2 residency inversion with CORRECT mechanics. R13's 256-bit
// v8.b32 hinted accesses hit an L1tex slow path (L1 74%, 32us) -- the
// literal ::evict_* qualifiers require 256-bit, but the
// createpolicy + ::cache_hint form accepts any width. This round:
// R8's proven fast structure (no smem, no syncs, 20.6us kernel) with
//   input  loads : ld.global.nc.L2::cache_hint (policy evict_first)
//   output stores: st.global.L2::cache_hint    (policy evict_last)
// Goal: output (66.8MB < 126MB L2) becomes the L2-resident set across
// graph replays; dirty lines re-dirtied in place; DRAM becomes a
// read-dominated ~67MB/replay stream instead of write-dominated ~87MB.
// sigmoid via MUFU.TANH: sig(x) = fma(0.5, tanh(0.5x), 0.5).

#define NT 256

__device__ __forceinline__ float sigf(float v) {
    float t;
    asm("tanh.approx.f32 %0, %1;" : "=f"(t) : "f"(v * 0.5f));
    return fmaf(0.5f, t, 0.5f);
}

__device__ __forceinline__ float ld_ef(const float* p, unsigned long long pol) {
    float v;
    asm("ld.global.nc.L2::cache_hint.f32 %0, [%1], %2;"
        : "=f"(v) : "l"(p), "l"(pol));
    return v;
}
__device__ __forceinline__ void st_el4(float4* p, float4 v, unsigned long long pol) {
    asm volatile("st.global.L2::cache_hint.v4.f32 [%0], {%1,%2,%3,%4}, %5;"
                 :: "l"(p), "f"(v.x), "f"(v.y), "f"(v.z), "f"(v.w), "l"(pol)
                 : "memory");
}
__device__ __forceinline__ void st_el1(float* p, float v, unsigned long long pol) {
    asm volatile("st.global.L2::cache_hint.f32 [%0], %1, %2;"
                 :: "l"(p), "f"(v), "l"(pol) : "memory");
}

__global__ __launch_bounds__(NT) void yolo_kernel(
    const float* __restrict__ x,
    const float* __restrict__ anchors,
    float* __restrict__ out)
{
    constexpr int A    = 3;
    constexpr int CH   = 85;
    constexpr int P    = 64 * 64;                     // 4096 positions per (b,a)
    constexpr int Btot = 16;
    constexpr int CONF_OFF = Btot * A * P * 4;        // 786432
    constexpr int CLS_OFF  = CONF_OFF + Btot * A * P; // 983040
    constexpr int CLS_BLKS = Btot * A * (P / 128);    // 1536 (128 positions/block)

    unsigned long long pol_ef, pol_el;
    asm("createpolicy.fractional.L2::evict_first.b64 %0, 1.0;" : "=l"(pol_ef));
    asm("createpolicy.fractional.L2::evict_last.b64 %0, 1.0;"  : "=l"(pol_el));

    const int blk = blockIdx.x;
    const int t   = threadIdx.x;

    if (blk < CLS_BLKS) {
        // ---- cls: 128 positions x 80 channels per block ----
        // thread=(p, j0): warp loads = 2 channels x 16 consecutive p
        // (2x64B segments per LDG); stores = even/odd lane pairs form
        // 32B-contiguous chunks per position (sector-perfect STG.128).
        const int ba = blk >> 5;                      // 32 tiles per (b,a)
        const int pg = ((blk & 31) << 7) + (t >> 1);  // global position
        const int j0 = t & 1;                         // chunk parity
        const float* xin = x + (size_t)ba * CH * P + pg;
        float4* ocls = reinterpret_cast<float4*>(
            out + CLS_OFF + (size_t)(ba * P + pg) * 80);
        #pragma unroll
        for (int k = 0; k < 10; k++) {
            const int j = 2 * k + j0;                 // float4 chunk 0..19
            const int c = 5 + 4 * j;                  // channels c..c+3
            float4 v;
            v.x = sigf(ld_ef(xin + (size_t)(c + 0) * P, pol_ef));
            v.y = sigf(ld_ef(xin + (size_t)(c + 1) * P, pol_ef));
            v.z = sigf(ld_ef(xin + (size_t)(c + 2) * P, pol_ef));
            v.w = sigf(ld_ef(xin + (size_t)(c + 3) * P, pol_ef));
            st_el4(ocls + j, v, pol_el);
        }
    } else {
        // ---- boxes + conf: 256 positions per block, thread = position ----
        const int b2 = blk - CLS_BLKS;
        const int ba = b2 >> 4;                       // 16 tiles per (b,a)
        const int pg = ((b2 & 15) << 8) + t;
        const int a  = ba - (ba / A) * A;
        const float aw = __ldg(anchors + a * 2 + 0);
        const float ah = __ldg(anchors + a * 2 + 1);
        const float* xin = x + (size_t)ba * CH * P + pg;
        const float x0 = ld_ef(xin + 0 * P, pol_ef);
        const float x1 = ld_ef(xin + 1 * P, pol_ef);
        const float x2 = ld_ef(xin + 2 * P, pol_ef);
        const float x3 = ld_ef(xin + 3 * P, pol_ef);
        const float x4 = ld_ef(xin + 4 * P, pol_ef);
        float4 b;
        b.x = (sigf(x0) + (float)(pg >> 6)) * (1.0f / 64.0f);
        b.y = (sigf(x1) + (float)(pg & 63)) * (1.0f / 64.0f);
        b.z = __expf(x2) * aw;
        b.w = __expf(x3) * ah;
        st_el4(reinterpret_cast<float4*>(out) + ba * P + pg, b, pol_el);
        st_el1(out + CONF_OFF + ba * P + pg, sigf(x4), pol_el);
    }
}

extern "C" void kernel_launch(void* const* d_in, const int* in_sizes, int n_in,
                              void* d_out, int out_size) {
    const float* x       = (const float*)d_in[0];
    const float* anchors = (const float*)d_in[1];
    float*       out     = (float*)d_out;
    // 1536 cls blocks + 768 boxes/conf blocks
    yolo_kernel<<<2304, NT>>>(x, anchors, out);
}